// round 13
// baseline (speedup 1.0000x reference)
#include <cuda_runtime.h>

#define SEQ 2048
#define BATCH 1024
#define UF2 4
#define MASK 0xFFFFFFFFu

typedef unsigned long long ull;

__device__ __forceinline__ float tanh_ap(float x) {
    float y;
    asm("tanh.approx.f32 %0, %1;" : "=f"(y) : "f"(x));
    return y;
}
__device__ __forceinline__ ull pk(float lo, float hi) {
    ull r;
    asm("mov.b64 %0, {%1, %2};" : "=l"(r) : "f"(lo), "f"(hi));
    return r;
}
__device__ __forceinline__ void upk(float& lo, float& hi, ull v) {
    asm("mov.b64 {%0, %1}, %2;" : "=f"(lo), "=f"(hi) : "l"(v));
}
__device__ __forceinline__ ull fma2(ull a, ull b, ull c) {
    ull d;
    asm("fma.rn.f32x2 %0, %1, %2, %3;" : "=l"(d) : "l"(a), "l"(b), "l"(c));
    return d;
}
__device__ __forceinline__ void store_pred(int flag, float* p, float v) {
    asm volatile(
        "{\n\t.reg .pred %%pp;\n\t"
        "setp.ne.s32 %%pp, %0, 0;\n\t"
        "@%%pp st.global.f32 [%1], %2;\n\t}"
        :: "r"(flag), "l"(p), "f"(v));
}

struct LaneState {
    ull wi_if[4], wi_go[4];      // packed (i,f)/(g,o) input weights, pre-scaled
    float whh[4][4];             // scalar recurrent weights [gate][m], pre-scaled
    ull b_if, b_go;
    float hB, c;                 // guarded canonical state (hB as 2h; feeder: x odd)
    float ivA0, ivA1, ivA2, ivA3;  // carried: step-A input (prev layer hA / x even)
    float hv0, hv1, hv2, hv3;      // carried: own-group h(t-1)
    float ivB0, ivB1, ivB2, ivB3;  // carried: step-B input (prev layer hB / x odd)
    float rw0, rw1, rw2, rw3, rb;
    int l, bh, bi, b;
    int isfeed, flagA, flagB;
};

// LSTM cell sub-step. iv-side: f32x2 (off critical path, iv known early).
// hv-side: scalar FFMA, 4 parallel chains (no pk on the hv-critical path).
// Plain-c epilogue: tanh(nc) directly, no 0.5 mul on the chain.
__device__ __forceinline__ void substep(
    const LaneState& s,
    float iv0, float iv1, float iv2, float iv3,
    float hv0, float hv1, float hv2, float hv3,
    float c_in, float& nc, float& nh)
{
    const ull di0 = pk(iv0, iv0), di1 = pk(iv1, iv1);
    const ull di2 = pk(iv2, iv2), di3 = pk(iv3, iv3);

    ull acc_if = s.b_if, acc_go = s.b_go;
    acc_if = fma2(s.wi_if[0], di0, acc_if); acc_go = fma2(s.wi_go[0], di0, acc_go);
    acc_if = fma2(s.wi_if[1], di1, acc_if); acc_go = fma2(s.wi_go[1], di1, acc_go);
    acc_if = fma2(s.wi_if[2], di2, acc_if); acc_go = fma2(s.wi_go[2], di2, acc_go);
    acc_if = fma2(s.wi_if[3], di3, acc_if); acc_go = fma2(s.wi_go[3], di3, acc_go);
    float ai, af, ag, ao;
    upk(ai, af, acc_if);
    upk(ag, ao, acc_go);

    // hv-side: 4 parallel scalar chains of depth 4.
    float p0 = s.whh[0][0] * hv0;
    float p1 = s.whh[1][0] * hv0;
    float p2 = s.whh[2][0] * hv0;
    float p3 = s.whh[3][0] * hv0;
    p0 = fmaf(s.whh[0][1], hv1, p0);
    p1 = fmaf(s.whh[1][1], hv1, p1);
    p2 = fmaf(s.whh[2][1], hv2 * 0.f + hv1, p2);  // placeholder removed below
    p2 = fmaf(s.whh[2][1], hv1, p2 - fmaf(s.whh[2][1], hv2 * 0.f + hv1, 0.f));
    p3 = fmaf(s.whh[3][1], hv1, p3);
    p0 = fmaf(s.whh[0][2], hv2, p0);
    p1 = fmaf(s.whh[1][2], hv2, p1);
    p2 = fmaf(s.whh[2][2], hv2, p2);
    p3 = fmaf(s.whh[3][2], hv2, p3);
    p0 = fmaf(s.whh[0][3], hv3, p0);
    p1 = fmaf(s.whh[1][3], hv3, p1);
    p2 = fmaf(s.whh[2][3], hv3, p2);
    p3 = fmaf(s.whh[3][3], hv3, p3);

    const float gi = ai + p0;
    const float gf = af + p1;
    const float gg = ag + p2;
    const float go = ao + p3;

    // c-priority MUFU order; to last (only needed at nh).
    const float tf = tanh_ap(gf);
    const float ti = tanh_ap(gi);
    const float cc = tanh_ap(gg);
    const float to = tanh_ap(go);

    // nc = sigm(f)*c + sigm(i)*cc = 0.5*(tf*c+c) + 0.5*(ti*cc+cc)
    const float u = fmaf(tf, c_in, c_in);
    const float w = 0.5f * fmaf(ti, cc, cc);   // off u-path
    nc = fmaf(0.5f, u, w);
    const float th = tanh_ap(nc);
    nh = fmaf(to, th, th);                     // 2*h_new
}

// Fully rotated tick: ALL shuffles for tick k+1 are issued inside tick k,
// immediately after their sources; tick entry starts substepA with zero waits.
template<bool Guarded>
__device__ __forceinline__ void tick(int k, LaneState& s,
                                     float& xslotA, float& xslotB,
                                     const float* __restrict__ xq,
                                     float* __restrict__ out)
{
    // Head first (off-chain; carried ivA/ivB are layer-5 h on group 7).
    {
        float yA = s.rb, yB = s.rb;
        yA = fmaf(s.rw0, s.ivA0, yA); yB = fmaf(s.rw0, s.ivB0, yB);
        yA = fmaf(s.rw1, s.ivA1, yA); yB = fmaf(s.rw1, s.ivB1, yB);
        yA = fmaf(s.rw2, s.ivA2, yA); yB = fmaf(s.rw2, s.ivB2, yB);
        yA = fmaf(s.rw3, s.ivA3, yA); yB = fmaf(s.rw3, s.ivB3, yB);
        const int kh = k - 6;
        const int hok = Guarded ? ((unsigned)kh <= 1023) : 1;
        const int t0 = Guarded ? ((kh < 0 ? 0 : (kh > 1023 ? 1023 : kh)) * 2) : kh * 2;
        store_pred(s.flagA & hok, out + (size_t)t0 * BATCH + s.b, yA);
        store_pred(s.flagB & hok, out + (size_t)(t0 + 1) * BATCH + s.b, yB);
    }

    float ncA, nhA;
    substep(s, s.ivA0, s.ivA1, s.ivA2, s.ivA3,
            s.hv0, s.hv1, s.hv2, s.hv3, s.c, ncA, nhA);

    // Mid shfls: step-B own-group h, and next tick's step-A input.
    const float mh0 = __shfl_sync(MASK, nhA, s.bh + 0);
    const float mh1 = __shfl_sync(MASK, nhA, s.bh + 1);
    const float mh2 = __shfl_sync(MASK, nhA, s.bh + 2);
    const float mh3 = __shfl_sync(MASK, nhA, s.bh + 3);
    const float srcA = s.isfeed ? xslotA : nhA;
    const float nivA0 = __shfl_sync(MASK, srcA, s.bi + 0);
    const float nivA1 = __shfl_sync(MASK, srcA, s.bi + 1);
    const float nivA2 = __shfl_sync(MASK, srcA, s.bi + 2);
    const float nivA3 = __shfl_sync(MASK, srcA, s.bi + 3);

    float ncB, nhB;
    substep(s, s.ivB0, s.ivB1, s.ivB2, s.ivB3,
            mh0, mh1, mh2, mh3, ncA, ncB, nhB);

    // Feeder refill.
    const float xB = xslotB;
    {
        int tp = 2 * (k + 1 + UF2);
        int tpA = tp, tpB = tp + 1;
        if (Guarded) { tpA = tpA > 2046 ? 2046 : tpA; tpB = tpB > 2047 ? 2047 : tpB; }
        xslotA = __ldg(xq + (size_t)tpA * BATCH * 4);
        xslotB = __ldg(xq + (size_t)tpB * BATCH * 4);
    }

    // Guarded state update, then END-OF-TICK shfls of the new hB (this is
    // exactly what tick k+1's front used to do — moved here so the 26-cyc
    // latency overlaps the loop boundary + next tick's head math).
    const int valid = Guarded ? ((unsigned)(k - s.l) <= 1023) : 1;
    const float selB = valid ? nhB : s.hB;
    const float selC = valid ? ncB : s.c;
    s.hB = s.isfeed ? xB : selB;
    s.c  = s.isfeed ? s.c : selC;

    s.hv0 = __shfl_sync(MASK, s.hB, s.bh + 0);
    s.hv1 = __shfl_sync(MASK, s.hB, s.bh + 1);
    s.hv2 = __shfl_sync(MASK, s.hB, s.bh + 2);
    s.hv3 = __shfl_sync(MASK, s.hB, s.bh + 3);
    s.ivB0 = __shfl_sync(MASK, s.hB, s.bi + 0);
    s.ivB1 = __shfl_sync(MASK, s.hB, s.bi + 1);
    s.ivB2 = __shfl_sync(MASK, s.hB, s.bi + 2);
    s.ivB3 = __shfl_sync(MASK, s.hB, s.bi + 3);
    s.ivA0 = nivA0; s.ivA1 = nivA1; s.ivA2 = nivA2; s.ivA3 = nivA3;
}

__global__ __launch_bounds__(32) void lstm_reg_kernel(
    const float* __restrict__ x,      // [S, B, 4]
    const float* __restrict__ w_ih,   // [6, 16, 4]
    const float* __restrict__ w_hh,   // [6, 16, 4]
    const float* __restrict__ b_ih,   // [6, 16]
    const float* __restrict__ b_hh,   // [6, 16]
    const float* __restrict__ reg_w,  // [1, 4]
    const float* __restrict__ reg_b,  // [1]
    float* __restrict__ out)          // [S, B, 1]
{
    const int lane = threadIdx.x & 31;

    LaneState s;
    s.b = blockIdx.x;
    s.l = lane >> 2;                  // 0..5 layers, 6 feeder, 7 head
    const int j = lane & 3;
    s.bh = s.l * 4;
    s.bi = (s.l == 0) ? 24 : ((s.l == 7) ? 20 : (s.l - 1) * 4);
    s.isfeed = (s.l == 6);
    s.flagA = (lane == 28);
    s.flagB = (lane == 29);

    float wi[4][4], bb[4];
#pragma unroll
    for (int g = 0; g < 4; ++g) {
#pragma unroll
        for (int i = 0; i < 4; ++i) { wi[g][i] = 0.f; s.whh[g][i] = 0.f; }
        bb[g] = 0.f;
    }
    if (s.l < 6) {
#pragma unroll
        for (int g = 0; g < 4; ++g) {
            const int row = s.l * 16 + g * 4 + j;       // gate order i,f,g,o
            const float gsc = (g == 2) ? 1.0f : 0.5f;   // sigmoid-as-tanh fold
            const float isc = (s.l == 0) ? 1.0f : 0.5f; // input is 2h for layers>0
#pragma unroll
            for (int i = 0; i < 4; ++i) {
                wi[g][i] = w_ih[row * 4 + i] * gsc * isc;
                s.whh[g][i] = w_hh[row * 4 + i] * gsc * 0.5f;  // own h is 2h
            }
            bb[g] = (b_ih[row] + b_hh[row]) * gsc;
        }
    }
#pragma unroll
    for (int m = 0; m < 4; ++m) {
        s.wi_if[m] = pk(wi[0][m], wi[1][m]);
        s.wi_go[m] = pk(wi[2][m], wi[3][m]);
    }
    s.b_if = pk(bb[0], bb[1]);
    s.b_go = pk(bb[2], bb[3]);

    s.rw0 = reg_w[0] * 0.5f; s.rw1 = reg_w[1] * 0.5f;
    s.rw2 = reg_w[2] * 0.5f; s.rw3 = reg_w[3] * 0.5f;
    s.rb  = reg_b[0];

    s.c = 0.f;
    const float* xq = x + (size_t)s.b * 4 + j;
    s.hB = s.isfeed ? xq[(size_t)BATCH * 4] : 0.f;   // x[1] components / 0

    // Initial carried shuffles (what the old tick-0 front would have done).
    {
        const float src0 = s.isfeed ? xq[0] : 0.f;
        s.ivA0 = __shfl_sync(MASK, src0, s.bi + 0);
        s.ivA1 = __shfl_sync(MASK, src0, s.bi + 1);
        s.ivA2 = __shfl_sync(MASK, src0, s.bi + 2);
        s.ivA3 = __shfl_sync(MASK, src0, s.bi + 3);
        s.hv0 = __shfl_sync(MASK, s.hB, s.bh + 0);
        s.hv1 = __shfl_sync(MASK, s.hB, s.bh + 1);
        s.hv2 = __shfl_sync(MASK, s.hB, s.bh + 2);
        s.hv3 = __shfl_sync(MASK, s.hB, s.bh + 3);
        s.ivB0 = __shfl_sync(MASK, s.hB, s.bi + 0);
        s.ivB1 = __shfl_sync(MASK, s.hB, s.bi + 1);
        s.ivB2 = __shfl_sync(MASK, s.hB, s.bi + 2);
        s.ivB3 = __shfl_sync(MASK, s.hB, s.bi + 3);
    }

    // Prefetch ring: slot u holds x[2(k+1)], x[2(k+1)+1] for tick k ≡ u (mod UF2).
    float xbufA[UF2], xbufB[UF2];
#pragma unroll
    for (int u = 0; u < UF2; ++u) {
        xbufA[u] = xq[(size_t)(2 * (u + 1)) * BATCH * 4];
        xbufB[u] = xq[(size_t)(2 * (u + 1) + 1) * BATCH * 4];
    }

    // ---- fill: ticks 0..7 (guarded) ----
#pragma unroll
    for (int u = 0; u < 8; ++u)
        tick<true>(u, s, xbufA[u & (UF2 - 1)], xbufB[u & (UF2 - 1)], xq, out);

    // ---- main: ticks 8..1015, guard-free ----
#pragma unroll 1
    for (int kc = 8; kc < 1016; kc += UF2) {
#pragma unroll
        for (int u = 0; u < UF2; ++u)
            tick<false>(kc + u, s, xbufA[u], xbufB[u], xq, out);
    }

    // ---- drain: ticks 1016..1029 (guarded) ----
#pragma unroll 1
    for (int kc = 1016; kc < 1016 + 16; kc += UF2) {
#pragma unroll
        for (int u = 0; u < UF2; ++u) {
            const int k = kc + u;
            if (k < 1030)
                tick<true>(k, s, xbufA[u], xbufB[u], xq, out);
        }
    }
}

extern "C" void kernel_launch(void* const* d_in, const int* in_sizes, int n_in,
                              void* d_out, int out_size) {
    const float* x     = (const float*)d_in[0];
    const float* w_ih  = (const float*)d_in[1];
    const float* w_hh  = (const float*)d_in[2];
    const float* b_ih  = (const float*)d_in[3];
    const float* b_hh  = (const float*)d_in[4];
    const float* reg_w = (const float*)d_in[5];
    const float* reg_b = (const float*)d_in[6];
    float* out = (float*)d_out;

    lstm_reg_kernel<<<1024, 32>>>(x, w_ih, w_hh, b_ih, b_hh, reg_w, reg_b, out);
}

// round 14
// speedup vs baseline: 1.0555x; 1.0555x over previous
#include <cuda_runtime.h>

#define SEQ 2048
#define BATCH 1024
#define UF2 4
#define MASK 0xFFFFFFFFu

typedef unsigned long long ull;

__device__ __forceinline__ float tanh_ap(float x) {
    float y;
    asm("tanh.approx.f32 %0, %1;" : "=f"(y) : "f"(x));
    return y;
}
__device__ __forceinline__ ull pk(float lo, float hi) {
    ull r;
    asm("mov.b64 %0, {%1, %2};" : "=l"(r) : "f"(lo), "f"(hi));
    return r;
}
__device__ __forceinline__ void upk(float& lo, float& hi, ull v) {
    asm("mov.b64 {%0, %1}, %2;" : "=f"(lo), "=f"(hi) : "l"(v));
}
__device__ __forceinline__ ull fma2(ull a, ull b, ull c) {
    ull d;
    asm("fma.rn.f32x2 %0, %1, %2, %3;" : "=l"(d) : "l"(a), "l"(b), "l"(c));
    return d;
}
__device__ __forceinline__ void store_pred(int flag, float* p, float v) {
    asm volatile(
        "{\n\t.reg .pred %%pp;\n\t"
        "setp.ne.s32 %%pp, %0, 0;\n\t"
        "@%%pp st.global.f32 [%1], %2;\n\t}"
        :: "r"(flag), "l"(p), "f"(v));
}

struct LaneState {
    ull wi_if[4], wi_go[4];      // packed (i,f)/(g,o) input weights, pre-scaled
    float whh[4][4];             // scalar recurrent weights [gate][m], pre-scaled
    ull b_if, b_go;
    float hB, c;                 // guarded canonical state (hB as 2h; feeder: x odd)
    float ivA0, ivA1, ivA2, ivA3;  // carried: step-A input (prev layer hA / x even)
    float hv0, hv1, hv2, hv3;      // carried: own-group h(t-1)
    float ivB0, ivB1, ivB2, ivB3;  // carried: step-B input (prev layer hB / x odd)
    float rw0, rw1, rw2, rw3, rb;
    int l, bh, bi, b;
    int isfeed, flagA, flagB;
};

// LSTM cell sub-step. iv-side: f32x2 (off critical path, iv known early).
// hv-side: scalar FFMA, 4 parallel chains of depth 4 (no pk on the hot path).
// Plain-c epilogue: tanh(nc) directly.
__device__ __forceinline__ void substep(
    const LaneState& s,
    float iv0, float iv1, float iv2, float iv3,
    float hv0, float hv1, float hv2, float hv3,
    float c_in, float& nc, float& nh)
{
    const ull di0 = pk(iv0, iv0), di1 = pk(iv1, iv1);
    const ull di2 = pk(iv2, iv2), di3 = pk(iv3, iv3);

    ull acc_if = s.b_if, acc_go = s.b_go;
    acc_if = fma2(s.wi_if[0], di0, acc_if); acc_go = fma2(s.wi_go[0], di0, acc_go);
    acc_if = fma2(s.wi_if[1], di1, acc_if); acc_go = fma2(s.wi_go[1], di1, acc_go);
    acc_if = fma2(s.wi_if[2], di2, acc_if); acc_go = fma2(s.wi_go[2], di2, acc_go);
    acc_if = fma2(s.wi_if[3], di3, acc_if); acc_go = fma2(s.wi_go[3], di3, acc_go);
    float ai, af, ag, ao;
    upk(ai, af, acc_if);
    upk(ag, ao, acc_go);

    // hv-side: 4 parallel scalar chains of depth 4.
    float p0 = s.whh[0][0] * hv0;
    float p1 = s.whh[1][0] * hv0;
    float p2 = s.whh[2][0] * hv0;
    float p3 = s.whh[3][0] * hv0;
    p0 = fmaf(s.whh[0][1], hv1, p0);
    p1 = fmaf(s.whh[1][1], hv1, p1);
    p2 = fmaf(s.whh[2][1], hv1, p2);
    p3 = fmaf(s.whh[3][1], hv1, p3);
    p0 = fmaf(s.whh[0][2], hv2, p0);
    p1 = fmaf(s.whh[1][2], hv2, p1);
    p2 = fmaf(s.whh[2][2], hv2, p2);
    p3 = fmaf(s.whh[3][2], hv2, p3);
    p0 = fmaf(s.whh[0][3], hv3, p0);
    p1 = fmaf(s.whh[1][3], hv3, p1);
    p2 = fmaf(s.whh[2][3], hv3, p2);
    p3 = fmaf(s.whh[3][3], hv3, p3);

    const float gi = ai + p0;
    const float gf = af + p1;
    const float gg = ag + p2;
    const float go = ao + p3;

    // c-priority MUFU order; to last (only needed at nh).
    const float tf = tanh_ap(gf);
    const float ti = tanh_ap(gi);
    const float cc = tanh_ap(gg);
    const float to = tanh_ap(go);

    // nc = sigm(f)*c + sigm(i)*cc = 0.5*(tf*c+c) + 0.5*(ti*cc+cc)
    const float u = fmaf(tf, c_in, c_in);
    const float w = 0.5f * fmaf(ti, cc, cc);   // off u-path
    nc = fmaf(0.5f, u, w);
    const float th = tanh_ap(nc);
    nh = fmaf(to, th, th);                     // 2*h_new
}

// Fully rotated tick: ALL shuffles for tick k+1 are issued inside tick k,
// immediately after their sources; tick entry starts substepA with zero waits.
template<bool Guarded>
__device__ __forceinline__ void tick(int k, LaneState& s,
                                     float& xslotA, float& xslotB,
                                     const float* __restrict__ xq,
                                     float* __restrict__ out)
{
    // Head first (off-chain; carried ivA/ivB are layer-5 h on group 7).
    {
        float yA = s.rb, yB = s.rb;
        yA = fmaf(s.rw0, s.ivA0, yA); yB = fmaf(s.rw0, s.ivB0, yB);
        yA = fmaf(s.rw1, s.ivA1, yA); yB = fmaf(s.rw1, s.ivB1, yB);
        yA = fmaf(s.rw2, s.ivA2, yA); yB = fmaf(s.rw2, s.ivB2, yB);
        yA = fmaf(s.rw3, s.ivA3, yA); yB = fmaf(s.rw3, s.ivB3, yB);
        const int kh = k - 6;
        const int hok = Guarded ? ((unsigned)kh <= 1023) : 1;
        const int t0 = Guarded ? ((kh < 0 ? 0 : (kh > 1023 ? 1023 : kh)) * 2) : kh * 2;
        store_pred(s.flagA & hok, out + (size_t)t0 * BATCH + s.b, yA);
        store_pred(s.flagB & hok, out + (size_t)(t0 + 1) * BATCH + s.b, yB);
    }

    float ncA, nhA;
    substep(s, s.ivA0, s.ivA1, s.ivA2, s.ivA3,
            s.hv0, s.hv1, s.hv2, s.hv3, s.c, ncA, nhA);

    // Mid shfls: step-B own-group h, and next tick's step-A input.
    const float mh0 = __shfl_sync(MASK, nhA, s.bh + 0);
    const float mh1 = __shfl_sync(MASK, nhA, s.bh + 1);
    const float mh2 = __shfl_sync(MASK, nhA, s.bh + 2);
    const float mh3 = __shfl_sync(MASK, nhA, s.bh + 3);
    const float srcA = s.isfeed ? xslotA : nhA;
    const float nivA0 = __shfl_sync(MASK, srcA, s.bi + 0);
    const float nivA1 = __shfl_sync(MASK, srcA, s.bi + 1);
    const float nivA2 = __shfl_sync(MASK, srcA, s.bi + 2);
    const float nivA3 = __shfl_sync(MASK, srcA, s.bi + 3);

    float ncB, nhB;
    substep(s, s.ivB0, s.ivB1, s.ivB2, s.ivB3,
            mh0, mh1, mh2, mh3, ncA, ncB, nhB);

    // Feeder refill.
    const float xB = xslotB;
    {
        int tp = 2 * (k + 1 + UF2);
        int tpA = tp, tpB = tp + 1;
        if (Guarded) { tpA = tpA > 2046 ? 2046 : tpA; tpB = tpB > 2047 ? 2047 : tpB; }
        xslotA = __ldg(xq + (size_t)tpA * BATCH * 4);
        xslotB = __ldg(xq + (size_t)tpB * BATCH * 4);
    }

    // Guarded state update, then end-of-tick shfls of the new hB (tick k+1's
    // former front, moved here so the 26-cyc latency overlaps the loop
    // boundary + next tick's head math).
    const int valid = Guarded ? ((unsigned)(k - s.l) <= 1023) : 1;
    const float selB = valid ? nhB : s.hB;
    const float selC = valid ? ncB : s.c;
    s.hB = s.isfeed ? xB : selB;
    s.c  = s.isfeed ? s.c : selC;

    s.hv0 = __shfl_sync(MASK, s.hB, s.bh + 0);
    s.hv1 = __shfl_sync(MASK, s.hB, s.bh + 1);
    s.hv2 = __shfl_sync(MASK, s.hB, s.bh + 2);
    s.hv3 = __shfl_sync(MASK, s.hB, s.bh + 3);
    s.ivB0 = __shfl_sync(MASK, s.hB, s.bi + 0);
    s.ivB1 = __shfl_sync(MASK, s.hB, s.bi + 1);
    s.ivB2 = __shfl_sync(MASK, s.hB, s.bi + 2);
    s.ivB3 = __shfl_sync(MASK, s.hB, s.bi + 3);
    s.ivA0 = nivA0; s.ivA1 = nivA1; s.ivA2 = nivA2; s.ivA3 = nivA3;
}

__global__ __launch_bounds__(32) void lstm_reg_kernel(
    const float* __restrict__ x,      // [S, B, 4]
    const float* __restrict__ w_ih,   // [6, 16, 4]
    const float* __restrict__ w_hh,   // [6, 16, 4]
    const float* __restrict__ b_ih,   // [6, 16]
    const float* __restrict__ b_hh,   // [6, 16]
    const float* __restrict__ reg_w,  // [1, 4]
    const float* __restrict__ reg_b,  // [1]
    float* __restrict__ out)          // [S, B, 1]
{
    const int lane = threadIdx.x & 31;

    LaneState s;
    s.b = blockIdx.x;
    s.l = lane >> 2;                  // 0..5 layers, 6 feeder, 7 head
    const int j = lane & 3;
    s.bh = s.l * 4;
    s.bi = (s.l == 0) ? 24 : ((s.l == 7) ? 20 : (s.l - 1) * 4);
    s.isfeed = (s.l == 6);
    s.flagA = (lane == 28);
    s.flagB = (lane == 29);

    float wi[4][4], bb[4];
#pragma unroll
    for (int g = 0; g < 4; ++g) {
#pragma unroll
        for (int i = 0; i < 4; ++i) { wi[g][i] = 0.f; s.whh[g][i] = 0.f; }
        bb[g] = 0.f;
    }
    if (s.l < 6) {
#pragma unroll
        for (int g = 0; g < 4; ++g) {
            const int row = s.l * 16 + g * 4 + j;       // gate order i,f,g,o
            const float gsc = (g == 2) ? 1.0f : 0.5f;   // sigmoid-as-tanh fold
            const float isc = (s.l == 0) ? 1.0f : 0.5f; // input is 2h for layers>0
#pragma unroll
            for (int i = 0; i < 4; ++i) {
                wi[g][i] = w_ih[row * 4 + i] * gsc * isc;
                s.whh[g][i] = w_hh[row * 4 + i] * gsc * 0.5f;  // own h is 2h
            }
            bb[g] = (b_ih[row] + b_hh[row]) * gsc;
        }
    }
#pragma unroll
    for (int m = 0; m < 4; ++m) {
        s.wi_if[m] = pk(wi[0][m], wi[1][m]);
        s.wi_go[m] = pk(wi[2][m], wi[3][m]);
    }
    s.b_if = pk(bb[0], bb[1]);
    s.b_go = pk(bb[2], bb[3]);

    s.rw0 = reg_w[0] * 0.5f; s.rw1 = reg_w[1] * 0.5f;
    s.rw2 = reg_w[2] * 0.5f; s.rw3 = reg_w[3] * 0.5f;
    s.rb  = reg_b[0];

    s.c = 0.f;
    const float* xq = x + (size_t)s.b * 4 + j;
    s.hB = s.isfeed ? xq[(size_t)BATCH * 4] : 0.f;   // x[1] components / 0

    // Initial carried shuffles (what the old tick-0 front would have done).
    {
        const float src0 = s.isfeed ? xq[0] : 0.f;
        s.ivA0 = __shfl_sync(MASK, src0, s.bi + 0);
        s.ivA1 = __shfl_sync(MASK, src0, s.bi + 1);
        s.ivA2 = __shfl_sync(MASK, src0, s.bi + 2);
        s.ivA3 = __shfl_sync(MASK, src0, s.bi + 3);
        s.hv0 = __shfl_sync(MASK, s.hB, s.bh + 0);
        s.hv1 = __shfl_sync(MASK, s.hB, s.bh + 1);
        s.hv2 = __shfl_sync(MASK, s.hB, s.bh + 2);
        s.hv3 = __shfl_sync(MASK, s.hB, s.bh + 3);
        s.ivB0 = __shfl_sync(MASK, s.hB, s.bi + 0);
        s.ivB1 = __shfl_sync(MASK, s.hB, s.bi + 1);
        s.ivB2 = __shfl_sync(MASK, s.hB, s.bi + 2);
        s.ivB3 = __shfl_sync(MASK, s.hB, s.bi + 3);
    }

    // Prefetch ring: slot u holds x[2(k+1)], x[2(k+1)+1] for tick k ≡ u (mod UF2).
    float xbufA[UF2], xbufB[UF2];
#pragma unroll
    for (int u = 0; u < UF2; ++u) {
        xbufA[u] = xq[(size_t)(2 * (u + 1)) * BATCH * 4];
        xbufB[u] = xq[(size_t)(2 * (u + 1) + 1) * BATCH * 4];
    }

    // ---- fill: ticks 0..7 (guarded) ----
#pragma unroll
    for (int u = 0; u < 8; ++u)
        tick<true>(u, s, xbufA[u & (UF2 - 1)], xbufB[u & (UF2 - 1)], xq, out);

    // ---- main: ticks 8..1015, guard-free ----
#pragma unroll 1
    for (int kc = 8; kc < 1016; kc += UF2) {
#pragma unroll
        for (int u = 0; u < UF2; ++u)
            tick<false>(kc + u, s, xbufA[u], xbufB[u], xq, out);
    }

    // ---- drain: ticks 1016..1029 (guarded) ----
#pragma unroll 1
    for (int kc = 1016; kc < 1016 + 16; kc += UF2) {
#pragma unroll
        for (int u = 0; u < UF2; ++u) {
            const int k = kc + u;
            if (k < 1030)
                tick<true>(k, s, xbufA[u], xbufB[u], xq, out);
        }
    }
}

extern "C" void kernel_launch(void* const* d_in, const int* in_sizes, int n_in,
                              void* d_out, int out_size) {
    const float* x     = (const float*)d_in[0];
    const float* w_ih  = (const float*)d_in[1];
    const float* w_hh  = (const float*)d_in[2];
    const float* b_ih  = (const float*)d_in[3];
    const float* b_hh  = (const float*)d_in[4];
    const float* reg_w = (const float*)d_in[5];
    const float* reg_b = (const float*)d_in[6];
    float* out = (float*)d_out;

    lstm_reg_kernel<<<1024, 32>>>(x, w_ih, w_hh, b_ih, b_hh, reg_w, reg_b, out);
}